// round 8
// baseline (speedup 1.0000x reference)
#include <cuda_runtime.h>
#include <cuda_bf16.h>
#include <stdint.h>

// ---------------------------------------------------------------------------
// out[b,i,j] = (x_i - x_j)^T M_b (x_i - x_j) = q_i + q_j - 2*G[b,i,j]
//   G = x M_b x^T,  q_i = G_ii.   B=16, N=D=256, fp32.
// Split-bf16 (hi/lo) mma.sync GEMMs, fp32 accum. M symmetric => no transposes.
// R8: M is NEVER split in global memory — gemm1 cp.asyncs raw f32 M chunks
//     and converts to swizzled bf16 h/l smem in-pipeline. Convert kernel now
//     handles x only. gemm2 unchanged (8 warps, 4-stage pipeline).
// ---------------------------------------------------------------------------

__device__ __align__(16) unsigned short g_Xh[256 * 256];
__device__ __align__(16) unsigned short g_Xl[256 * 256];
__device__ __align__(16) unsigned short g_Yh[16 * 256 * 256];
__device__ __align__(16) unsigned short g_Yl[16 * 256 * 256];
__device__ float g_q[16 * 256];

__device__ __forceinline__ uint32_t smem_u32(const void* p) {
    uint32_t a;
    asm("{ .reg .u64 t; cvta.to.shared.u64 t, %1; cvt.u32.u64 %0, t; }"
        : "=r"(a) : "l"(p));
    return a;
}

__device__ __forceinline__ void cp16(uint32_t dst, const void* src) {
    asm volatile("cp.async.cg.shared.global [%0], [%1], 16;"
                 :: "r"(dst), "l"(src) : "memory");
}
#define CP_COMMIT() asm volatile("cp.async.commit_group;" ::: "memory")
template <int N>
__device__ __forceinline__ void cp_wait() {
    asm volatile("cp.async.wait_group %0;" :: "n"(N) : "memory");
}

__device__ __forceinline__ void ldm_x4(uint32_t* r, uint32_t addr) {
    asm volatile("ldmatrix.sync.aligned.m8n8.x4.shared.b16 {%0,%1,%2,%3}, [%4];"
                 : "=r"(r[0]), "=r"(r[1]), "=r"(r[2]), "=r"(r[3]) : "r"(addr));
}
__device__ __forceinline__ void mma_bf16(float* d, const uint32_t* a,
                                         uint32_t b0, uint32_t b1) {
    asm volatile(
        "mma.sync.aligned.m16n8k16.row.col.f32.bf16.bf16.f32 "
        "{%0,%1,%2,%3}, {%4,%5,%6,%7}, {%8,%9}, {%0,%1,%2,%3};"
        : "+f"(d[0]), "+f"(d[1]), "+f"(d[2]), "+f"(d[3])
        : "r"(a[0]), "r"(a[1]), "r"(a[2]), "r"(a[3]), "r"(b0), "r"(b1));
}

__device__ __forceinline__ void split_pack(float v0, float v1,
                                           uint32_t& ph, uint32_t& pl) {
    const __nv_bfloat16 h0 = __float2bfloat16(v0);
    const __nv_bfloat16 h1 = __float2bfloat16(v1);
    const __nv_bfloat16 e0 = __float2bfloat16(v0 - __bfloat162float(h0));
    const __nv_bfloat16 e1 = __float2bfloat16(v1 - __bfloat162float(h1));
    ph = (uint32_t)__bfloat16_as_ushort(h0) | ((uint32_t)__bfloat16_as_ushort(h1) << 16);
    pl = (uint32_t)__bfloat16_as_ushort(e0) | ((uint32_t)__bfloat16_as_ushort(e1) << 16);
}

// ---------------------------------------------------------------------------
// Mini convert: x only (65536 floats, 8 per thread); zeroes g_q.
// ---------------------------------------------------------------------------
__global__ void __launch_bounds__(256) k_convx(const float* __restrict__ x) {
    const int t = blockIdx.x * 256 + threadIdx.x;   // 0..8191
    if (t < 16 * 256) g_q[t] = 0.0f;

    const int u = t * 8;
    const float4 a = ((const float4*)(x + u))[0];
    const float4 c = ((const float4*)(x + u))[1];
    uint32_t ph[4], pl[4];
    split_pack(a.x, a.y, ph[0], pl[0]);
    split_pack(a.z, a.w, ph[1], pl[1]);
    split_pack(c.x, c.y, ph[2], pl[2]);
    split_pack(c.z, c.w, ph[3], pl[3]);
    *(uint4*)(g_Xh + u) = make_uint4(ph[0], ph[1], ph[2], ph[3]);
    *(uint4*)(g_Xl + u) = make_uint4(pl[0], pl[1], pl[2], pl[3]);
}

// ---------------------------------------------------------------------------
// GEMM: block tile 64x64, 256 threads = 8 warps (2 m-warps x 4 n-warps),
// warp tile 32x16, BK=32, 4-stage cp.async pipeline.
//   D += Ah*Bh + Ah*Bl + Al*Bh   (fp32 register accum)
// PHASE1 stage (24576B): Ah@0, Al@4096, Bh@8192, Bl@12288, Bf32@16384 (8KB).
//   B arrives as raw f32 M rows; converted in-pipeline to swizzled Bh/Bl.
// PHASE2 stage (16384B): Ah@0, Al@4096, Bh@8192, Bl@12288 (all pre-split).
// 16B-chunk swizzle c ^ ((row>>1)&3), 64B rows — conflict-free stores+ldmatrix.
// PHASE 1: A=x, B=M_b rows; epilogue -> Yh/Yl + fused partial q (atomics).
// PHASE 2: A=Y_b, B=x rows;  epilogue -> out = q_i + q_j - 2*acc.
// ---------------------------------------------------------------------------
#define STAGES   4
#define STG1     24576
#define STG2     16384
#define SMEM_B1  (STAGES * STG1 + 1024)
#define SMEM_B2  (STAGES * STG2 + 1024)

template <int PHASE>
__global__ void __launch_bounds__(256) k_gemm(const float* __restrict__ x,
                                              const float* __restrict__ M,
                                              float* __restrict__ out) {
    extern __shared__ __align__(128) unsigned char smem[];
    const uint32_t sb = smem_u32(smem);
    const int STG = (PHASE == 1) ? STG1 : STG2;
    const uint32_t QSO = STAGES * (uint32_t)STG;
    const int tid = threadIdx.x;
    const int wid = tid >> 5, l = tid & 31;
    const int wm  = wid & 1, wn = wid >> 1;      // 2 x 4 warp grid
    const int b   = blockIdx.z;
    const int bm0 = blockIdx.y * 64;
    const int bn0 = blockIdx.x * 64;

    const unsigned short *Ah, *Al, *Bh = nullptr, *Bl = nullptr;
    const float* BM = nullptr;
    if (PHASE == 1) {
        Ah = g_Xh + bm0 * 256;             Al = g_Xl + bm0 * 256;
        BM = M + (size_t)b * 65536 + bn0 * 256;
    } else {
        Ah = g_Yh + b * 65536 + bm0 * 256; Al = g_Yl + b * 65536 + bm0 * 256;
        Bh = g_Xh + bn0 * 256;             Bl = g_Xl + bn0 * 256;
    }

    if (PHASE == 2) {
        float* qs = (float*)(smem + QSO);
        qs[tid] = g_q[b * 256 + tid];
    }

    // one BK=32 chunk (kc 0..7) into stage s
    auto issue = [&](int kc, int s) {
        const uint32_t st = sb + s * STG;
        const int k0 = kc * 32;
        const int row = tid >> 2;
        const int c = tid & 3;
        const uint32_t d = st + row * 64 + ((c ^ ((row >> 1) & 3)) << 4);
        const int go = row * 256 + k0 + c * 8;
        cp16(d,        Ah + go);
        cp16(d + 4096, Al + go);
        if (PHASE == 1) {
            // raw f32 B rows into staging: thread covers 32B (2 chunks)
            const uint32_t df = st + 16384 + row * 128 + c * 32;
            const float* gsrc = BM + row * 256 + k0 + c * 8;
            cp16(df,      gsrc);
            cp16(df + 16, gsrc + 4);
        } else {
            cp16(d + 8192,  Bh + go);
            cp16(d + 12288, Bl + go);
        }
    };

    float acc[2][2][4] = {};   // [mt][n8 j][reg]

    issue(0, 0); CP_COMMIT();
    issue(1, 1); CP_COMMIT();
    issue(2, 2); CP_COMMIT();

    const int rA = (l & 15);                    // A: row within m16 tile
    const int hA = (l >> 4);                    // A: k8-half select
    const int rB = ((l >> 4) << 3) + (l & 7);   // B: n-row within n16 group
    const int hB = ((l >> 3) & 1);              // B: k8-half select

    for (int i = 0; i < 8; i++) {
        cp_wait<2>();
        __syncthreads();

        const uint32_t st = sb + (i & 3) * STG;

        if (PHASE == 1) {
            // convert stage i's f32 B rows -> swizzled bf16 Bh/Bl
            const int r  = tid >> 2;
            const int kh = tid & 3;
            const float4* fs = (const float4*)(smem + (size_t)(i & 3) * STG
                                               + 16384 + r * 128 + kh * 32);
            const float4 f0 = fs[0];
            const float4 f1 = fs[1];
            uint32_t ph[4], pl[4];
            split_pack(f0.x, f0.y, ph[0], pl[0]);
            split_pack(f0.z, f0.w, ph[1], pl[1]);
            split_pack(f1.x, f1.y, ph[2], pl[2]);
            split_pack(f1.z, f1.w, ph[3], pl[3]);
            const size_t dd = (size_t)(i & 3) * STG + 8192 + r * 64
                            + ((kh ^ ((r >> 1) & 3)) << 4);
            *(uint4*)(smem + dd)        = make_uint4(ph[0], ph[1], ph[2], ph[3]);
            *(uint4*)(smem + dd + 4096) = make_uint4(pl[0], pl[1], pl[2], pl[3]);
        }

        if (i + 3 < 8) issue(i + 3, (i + 3) & 3);
        CP_COMMIT();

        if (PHASE == 1) __syncthreads();   // Bh/Bl visible to all warps

        // hoist ALL fragments for both k-halves (12 independent ldmatrix)
        uint32_t ah[2][2][4], al[2][2][4], bh[2][4], bl[2][4];
        #pragma unroll
        for (int ks = 0; ks < 2; ks++) {
            #pragma unroll
            for (int mt = 0; mt < 2; mt++) {
                const int row = wm * 32 + mt * 16 + rA;
                const int c = (ks * 2 + hA) ^ ((row >> 1) & 3);
                const uint32_t a = st + row * 64 + (c << 4);
                ldm_x4(ah[ks][mt], a);
                ldm_x4(al[ks][mt], a + 4096);
            }
            {
                const int row = wn * 16 + rB;
                const int c = (ks * 2 + hB) ^ ((row >> 1) & 3);
                const uint32_t a = st + 8192 + row * 64 + (c << 4);
                ldm_x4(bh[ks], a);
                ldm_x4(bl[ks], a + 4096);
            }
        }
        #pragma unroll
        for (int ks = 0; ks < 2; ks++)
            #pragma unroll
            for (int mt = 0; mt < 2; mt++)
                #pragma unroll
                for (int j = 0; j < 2; j++) {
                    const int o = j * 2;
                    mma_bf16(acc[mt][j], ah[ks][mt], bh[ks][o], bh[ks][o + 1]);
                    mma_bf16(acc[mt][j], ah[ks][mt], bl[ks][o], bl[ks][o + 1]);
                    mma_bf16(acc[mt][j], al[ks][mt], bh[ks][o], bh[ks][o + 1]);
                }
    }

    // ------------------------------------------------------------------ epi
    const int lr = l >> 2;          // 0..7
    const int lc = (l & 3) * 2;     // 0,2,4,6

    if (PHASE == 1) {
        unsigned short* yh = g_Yh + b * 65536;
        unsigned short* yl = g_Yl + b * 65536;
        #pragma unroll
        for (int mt = 0; mt < 2; mt++)
            #pragma unroll
            for (int half = 0; half < 2; half++) {
                const int row = bm0 + wm * 32 + mt * 16 + lr + half * 8;
                float qpart = 0.0f;
                #pragma unroll
                for (int j = 0; j < 2; j++) {
                    const int col = bn0 + wn * 16 + j * 8 + lc;
                    const float v0 = acc[mt][j][half * 2 + 0];
                    const float v1 = acc[mt][j][half * 2 + 1];
                    const float2 xv = *(const float2*)(x + row * 256 + col);
                    qpart += v0 * xv.x + v1 * xv.y;
                    uint32_t ph, pl;
                    split_pack(v0, v1, ph, pl);
                    *(uint32_t*)(yh + row * 256 + col) = ph;
                    *(uint32_t*)(yl + row * 256 + col) = pl;
                }
                qpart += __shfl_xor_sync(0xffffffffu, qpart, 1);
                qpart += __shfl_xor_sync(0xffffffffu, qpart, 2);
                if ((l & 3) == 0) atomicAdd(g_q + b * 256 + row, qpart);
            }
    } else {
        const float* qs = (const float*)(smem + QSO);
        float* ob = out + ((size_t)b << 16);
        #pragma unroll
        for (int mt = 0; mt < 2; mt++)
            #pragma unroll
            for (int j = 0; j < 2; j++) {
                const int col = bn0 + wn * 16 + j * 8 + lc;
                const float qj0 = qs[col], qj1 = qs[col + 1];
                #pragma unroll
                for (int half = 0; half < 2; half++) {
                    const int row = bm0 + wm * 32 + mt * 16 + lr + half * 8;
                    const float qi = qs[row];
                    float2 v;
                    v.x = qi + qj0 - 2.0f * acc[mt][j][half * 2 + 0];
                    v.y = qi + qj1 - 2.0f * acc[mt][j][half * 2 + 1];
                    *(float2*)(ob + row * 256 + col) = v;
                }
            }
    }
}

// ---------------------------------------------------------------------------
extern "C" void kernel_launch(void* const* d_in, const int* in_sizes, int n_in,
                              void* d_out, int out_size) {
    const float* x = (const float*)d_in[0];   // (256, 256) f32
    const float* M = (const float*)d_in[1];   // (16, 256, 256) f32
    float* out = (float*)d_out;               // (16, 256, 256) f32
    (void)in_sizes; (void)n_in; (void)out_size;

    (void)cudaFuncSetAttribute(k_gemm<1>, cudaFuncAttributeMaxDynamicSharedMemorySize, SMEM_B1);
    (void)cudaFuncSetAttribute(k_gemm<2>, cudaFuncAttributeMaxDynamicSharedMemorySize, SMEM_B2);

    k_convx<<<32, 256>>>(x);
    k_gemm<1><<<dim3(4, 4, 16), 256, SMEM_B1>>>(x, M, nullptr);
    k_gemm<2><<<dim3(4, 4, 16), 256, SMEM_B2>>>(x, M, out);
}